// round 4
// baseline (speedup 1.0000x reference)
#include <cuda_runtime.h>
#include <math.h>

#define KK 128
#define ADIM 64
#define LDUR 6
#define TT 60
#define BSZ 1024
#define TH2 1024
#define NEGINF -1e38f

// ---------------- scratch (static device, no allocations) ----------------
__device__ float g_h[(size_t)BSZ * (KK * ADIM)];          // 1024 x 8192  (32 MB)
__device__ float g_cond[(size_t)BSZ * (KK * ADIM * 2)];   // 1024 x 16384 (64 MB)
__device__ float g_pi[BSZ * KK];                          // 512 KB
__device__ float g_tsc[KK * KK];                          // 64 KB
__device__ float g_P[(size_t)BSZ * KK * KK];              // 64 MB

// ---------------- pi = log_softmax(uniqenc @ W_init + b) ----------------
__global__ __launch_bounds__(128) void pi_kernel(
    const float* __restrict__ uniq, const float* __restrict__ W,
    const float* __restrict__ b, float* __restrict__ pi)
{
    __shared__ float u[TH2];
    __shared__ float red[128];
    int bidx = blockIdx.x, k = threadIdx.x;
    for (int i = k; i < TH2; i += 128) u[i] = uniq[bidx * TH2 + i];
    __syncthreads();
    float acc = 0.f;
#pragma unroll 8
    for (int i = 0; i < TH2; i++) acc += u[i] * W[i * KK + k];
    acc += b[k];
    // block log-softmax over 128
    red[k] = acc; __syncthreads();
    for (int s = 64; s > 0; s >>= 1) { if (k < s) red[k] = fmaxf(red[k], red[k + s]); __syncthreads(); }
    float m = red[0]; __syncthreads();
    float e = expf(acc - m);
    red[k] = e; __syncthreads();
    for (int s = 64; s > 0; s >>= 1) { if (k < s) red[k] += red[k + s]; __syncthreads(); }
    float ssum = red[0];
    pi[bidx * KK + k] = acc - m - logf(ssum);
}

// ---------------- tscores = A_from @ A_to + diag(NEGINF) ----------------
__global__ __launch_bounds__(128) void tsc_kernel(
    const float* __restrict__ Af, const float* __restrict__ At, float* __restrict__ tsc)
{
    int k = blockIdx.x, j = threadIdx.x;
    float acc = 0.f;
#pragma unroll
    for (int a = 0; a < ADIM; a++) acc += Af[k * ADIM + a] * At[a * KK + j];
    if (k == j) acc += NEGINF;
    tsc[k * KK + j] = acc;
}

// ---------------- tiled fp32 GEMM: C = op(A @ B + bias) ----------------
// A: MxKd row-major, B: KdxN row-major. BM=BN=128, BK=8, 256 threads, 8x8 tiles.
__global__ __launch_bounds__(256) void sgemm_kernel(
    const float* __restrict__ A, const float* __restrict__ B,
    const float* __restrict__ bias, float* __restrict__ C,
    int M, int N, int Kd, int do_relu)
{
    const int BM = 128, BN = 128, BK = 8;
    __shared__ float As[BK][BM];
    __shared__ float Bs[BK][BN];
    int tid = threadIdx.x;
    int tx = tid & 15, ty = tid >> 4;
    int m0 = blockIdx.y * BM, n0 = blockIdx.x * BN;
    float acc[8][8];
#pragma unroll
    for (int i = 0; i < 8; i++)
#pragma unroll
        for (int j = 0; j < 8; j++) acc[i][j] = 0.f;

    int arow = tid >> 1;            // 0..127
    int acol = (tid & 1) * 4;       // 0 or 4
    int brow = tid >> 5;            // 0..7
    int bcol = (tid & 31) * 4;      // 0..124
    const float* Aptr = A + (size_t)(m0 + arow) * Kd + acol;
    const float* Bptr = B + (size_t)brow * N + (n0 + bcol);

    for (int k0 = 0; k0 < Kd; k0 += BK) {
        float4 av = *(const float4*)(Aptr);
        float4 bv = *(const float4*)(Bptr);
        As[acol + 0][arow] = av.x;
        As[acol + 1][arow] = av.y;
        As[acol + 2][arow] = av.z;
        As[acol + 3][arow] = av.w;
        *(float4*)&Bs[brow][bcol] = bv;
        __syncthreads();
#pragma unroll
        for (int kk = 0; kk < BK; kk++) {
            float ra[8], rb[8];
            float4 a0 = *(const float4*)&As[kk][ty * 8];
            float4 a1 = *(const float4*)&As[kk][ty * 8 + 4];
            float4 b0 = *(const float4*)&Bs[kk][tx * 8];
            float4 b1 = *(const float4*)&Bs[kk][tx * 8 + 4];
            ra[0]=a0.x; ra[1]=a0.y; ra[2]=a0.z; ra[3]=a0.w; ra[4]=a1.x; ra[5]=a1.y; ra[6]=a1.z; ra[7]=a1.w;
            rb[0]=b0.x; rb[1]=b0.y; rb[2]=b0.z; rb[3]=b0.w; rb[4]=b1.x; rb[5]=b1.y; rb[6]=b1.z; rb[7]=b1.w;
#pragma unroll
            for (int i = 0; i < 8; i++)
#pragma unroll
                for (int j = 0; j < 8; j++) acc[i][j] += ra[i] * rb[j];
        }
        __syncthreads();
        Aptr += BK;
        Bptr += (size_t)BK * N;
    }
#pragma unroll
    for (int i = 0; i < 8; i++) {
        int m = m0 + ty * 8 + i;
#pragma unroll
        for (int j4 = 0; j4 < 2; j4++) {
            int n = n0 + tx * 8 + j4 * 4;
            float4 v;
            v.x = acc[i][j4 * 4 + 0] + bias[n + 0];
            v.y = acc[i][j4 * 4 + 1] + bias[n + 1];
            v.z = acc[i][j4 * 4 + 2] + bias[n + 2];
            v.w = acc[i][j4 * 4 + 3] + bias[n + 3];
            if (do_relu) {
                v.x = fmaxf(v.x, 0.f); v.y = fmaxf(v.y, 0.f);
                v.z = fmaxf(v.z, 0.f); v.w = fmaxf(v.w, 0.f);
            }
            *(float4*)&C[(size_t)m * N + n] = v;
        }
    }
}

// ---------------- trans: P[b,k,j] = softmax_j(tsc[k,j] + from[b,k,:].to[b,j,:]) ----------------
// Dynamic smem: 64 KB. Phase 1 uses it as fr/to staging (2*128*64 floats);
// phase 2 reuses the SAME region as the 128x128 score tile (accumulators are
// in registers across the boundary).
__global__ __launch_bounds__(256) void trans_kernel(
    const float* __restrict__ cond, const float* __restrict__ tsc, float* __restrict__ P)
{
    extern __shared__ float sm[];
    float* fr = sm;                      // 128*64
    float* to = sm + KK * ADIM;          // 128*64
    float* tr = sm;                      // 128*128 (aliases fr/to after phase 1)
    int b = blockIdx.x, tid = threadIdx.x;
    const float* cb = cond + (size_t)b * KK * 2 * ADIM;
    for (int idx = tid; idx < KK * 2 * ADIM; idx += 256) {
        int kk = idx >> 7;
        int a = idx & 127;
        float v = cb[idx];
        if (a < ADIM) fr[kk * ADIM + a] = v;
        else          to[kk * ADIM + (a - ADIM)] = v;
    }
    __syncthreads();
    int tx = tid & 15, ty = tid >> 4;
    float acc[8][8];
#pragma unroll
    for (int i = 0; i < 8; i++)
#pragma unroll
        for (int j = 0; j < 8; j++) acc[i][j] = 0.f;
#pragma unroll 4
    for (int a = 0; a < ADIM; a++) {
        float ra[8], rb[8];
#pragma unroll
        for (int i = 0; i < 8; i++) ra[i] = fr[(ty * 8 + i) * ADIM + a];
#pragma unroll
        for (int j = 0; j < 8; j++) rb[j] = to[(tx * 8 + j) * ADIM + a];
#pragma unroll
        for (int i = 0; i < 8; i++)
#pragma unroll
            for (int j = 0; j < 8; j++) acc[i][j] += ra[i] * rb[j];
    }
    __syncthreads();   // phase boundary: fr/to dead, tr takes over the buffer
#pragma unroll
    for (int i = 0; i < 8; i++) {
        int row = ty * 8 + i;
#pragma unroll
        for (int j = 0; j < 8; j++) {
            int col = tx * 8 + j;
            tr[row * KK + col] = acc[i][j] + tsc[row * KK + col];
        }
    }
    __syncthreads();
    // row softmax -> write probabilities
    int wid = tid >> 5, lane = tid & 31;
    for (int row = wid; row < KK; row += 8) {
        float v[4]; float m = -INFINITY;
#pragma unroll
        for (int i = 0; i < 4; i++) { v[i] = tr[row * KK + lane + i * 32]; m = fmaxf(m, v[i]); }
#pragma unroll
        for (int off = 16; off; off >>= 1) m = fmaxf(m, __shfl_xor_sync(0xffffffffu, m, off));
        float e[4]; float s = 0.f;
#pragma unroll
        for (int i = 0; i < 4; i++) { e[i] = expf(v[i] - m); s += e[i]; }
#pragma unroll
        for (int off = 16; off; off >>= 1) s += __shfl_xor_sync(0xffffffffu, s, off);
        float inv = 1.0f / s;
#pragma unroll
        for (int i = 0; i < 4; i++)
            P[(size_t)b * KK * KK + row * KK + lane + i * 32] = e[i] * inv;
    }
}

// ---------------- scan: per-batch-element forward recurrence ----------------
__global__ __launch_bounds__(128) void scan_kernel(
    const float* __restrict__ obs, const float* __restrict__ pi,
    const float* __restrict__ Pg, float* __restrict__ out)
{
    extern __shared__ float sm[];
    float* Psm  = sm;                 // 128*128
    float* buf  = sm + KK * KK;       // 6*128
    float* pvec = buf + LDUR * KK;    // 128
    float* red  = pvec + KK;          // 128
    int b = blockIdx.x, j = threadIdx.x;
    const float len_lp = -1.7917594692280550f;   // -log(6)

    // load P[b] (64 KB, coalesced float4)
    {
        const float4* src = (const float4*)(Pg + (size_t)b * KK * KK);
        float4* dst = (float4*)Psm;
        for (int i = j; i < KK * KK / 4; i += 128) dst[i] = src[i];
    }
    buf[0 * KK + j] = pi[b * KK + j];
#pragma unroll
    for (int l = 1; l < LDUR; l++) buf[l * KK + j] = NEGINF;
    __syncthreads();

    int base = 0;
    for (int t = 0; t < TT; t++) {
        // alpha_j = LSE_l( buf[l][j] + obs_seg(t,l)[j] + len_lp )
        float vs[LDUR];
        float vmax = -INFINITY;
#pragma unroll
        for (int l = 0; l < LDUR; l++) {
            int st = t - l;
            float v;
            if (st >= 0) {
                float o = obs[(((size_t)l * TT + st) * BSZ + b) * KK + j];
                v = buf[((base + l) % LDUR) * KK + j] + o + len_lp;
            } else {
                v = NEGINF;
            }
            vs[l] = v;
            vmax = fmaxf(vmax, v);
        }
        float alpha;
        if (vmax < -1e30f) alpha = NEGINF;
        else {
            float s = 0.f;
#pragma unroll
            for (int l = 0; l < LDUR; l++) s += expf(vs[l] - vmax);
            alpha = vmax + logf(s);
        }
        // block max of alpha
        red[j] = alpha; __syncthreads();
        for (int s2 = 64; s2; s2 >>= 1) { if (j < s2) red[j] = fmaxf(red[j], red[j + s2]); __syncthreads(); }
        float M = red[0];
        __syncthreads();
        pvec[j] = expf(alpha - M);
        __syncthreads();

        if (t == TT - 1) {
            // out[b] = LSE_j alpha = M + log(sum pvec)
            red[j] = pvec[j]; __syncthreads();
            for (int s2 = 64; s2; s2 >>= 1) { if (j < s2) red[j] += red[j + s2]; __syncthreads(); }
            if (j == 0) out[b] = M + logf(red[0]);
            break;
        }

        // astar_j = M + log( sum_k pvec[k] * P[k][j] )
        float a0 = 0.f, a1 = 0.f, a2 = 0.f, a3 = 0.f;
#pragma unroll 8
        for (int kk = 0; kk < KK; kk += 4) {
            a0 += pvec[kk + 0] * Psm[(kk + 0) * KK + j];
            a1 += pvec[kk + 1] * Psm[(kk + 1) * KK + j];
            a2 += pvec[kk + 2] * Psm[(kk + 2) * KK + j];
            a3 += pvec[kk + 3] * Psm[(kk + 3) * KK + j];
        }
        float astar = M + logf((a0 + a1) + (a2 + a3));

        base = (base + LDUR - 1) % LDUR;
        buf[base * KK + j] = astar;
        __syncthreads();
    }
}

// ---------------- launch ----------------
extern "C" void kernel_launch(void* const* d_in, const int* in_sizes, int n_in,
                              void* d_out, int out_size)
{
    const float* uniqenc = (const float*)d_in[0];
    const float* obs_lps = (const float*)d_in[1];
    const float* W_init  = (const float*)d_in[2];
    const float* b_init  = (const float*)d_in[3];
    const float* A_from  = (const float*)d_in[4];
    const float* A_to    = (const float*)d_in[5];
    const float* W_c1    = (const float*)d_in[6];
    const float* b_c1    = (const float*)d_in[7];
    const float* W_c2    = (const float*)d_in[8];
    const float* b_c2    = (const float*)d_in[9];
    float* out = (float*)d_out;

    float *p_h, *p_cond, *p_pi, *p_tsc, *p_P;
    cudaGetSymbolAddress((void**)&p_h, g_h);
    cudaGetSymbolAddress((void**)&p_cond, g_cond);
    cudaGetSymbolAddress((void**)&p_pi, g_pi);
    cudaGetSymbolAddress((void**)&p_tsc, g_tsc);
    cudaGetSymbolAddress((void**)&p_P, g_P);

    // capture-safe, called every time (no static guards per harness rules)
    cudaFuncSetAttribute(trans_kernel, cudaFuncAttributeMaxDynamicSharedMemorySize,
                         (2 * KK * ADIM) * (int)sizeof(float));
    cudaFuncSetAttribute(scan_kernel, cudaFuncAttributeMaxDynamicSharedMemorySize,
                         (KK * KK + LDUR * KK + 2 * KK) * (int)sizeof(float));

    // pi (independent)
    pi_kernel<<<BSZ, 128>>>(uniqenc, W_init, b_init, p_pi);
    // tscores (independent)
    tsc_kernel<<<KK, 128>>>(A_from, A_to, p_tsc);
    // h = relu(uniqenc @ W_c1 + b_c1):  1024 x 8192, Kd=1024
    {
        dim3 grid(8192 / 128, 1024 / 128);
        sgemm_kernel<<<grid, 256>>>(uniqenc, W_c1, b_c1, p_h, 1024, 8192, 1024, 1);
    }
    // cond = h @ W_c2 + b_c2:  1024 x 16384, Kd=8192
    {
        dim3 grid(16384 / 128, 1024 / 128);
        sgemm_kernel<<<grid, 256>>>(p_h, W_c2, b_c2, p_cond, 1024, 16384, 8192, 0);
    }
    // trans -> P
    trans_kernel<<<BSZ, 256, (2 * KK * ADIM) * sizeof(float)>>>(p_cond, p_tsc, p_P);
    // scan
    scan_kernel<<<BSZ, 128, (KK * KK + LDUR * KK + 2 * KK) * sizeof(float)>>>(obs_lps, p_pi, p_P, out);

    (void)in_sizes; (void)n_in; (void)out_size;
}